// round 16
// baseline (speedup 1.0000x reference)
#include <cuda_runtime.h>
#include <cuda_bf16.h>
#include <stdint.h>
#include <math.h>

// Problem constants
constexpr int cB  = 2;
constexpr int cS  = 2048;
constexpr int cH  = 1024;
constexpr int cNH = 16;
constexpr int cD  = 64;
constexpr int cM  = cB * cS;   // 4096

// bf16 split scratch (full splits everywhere — numerics frozen)
__device__ __nv_bfloat16 g_Qhi[(size_t)cB * cNH * cS * cD];
__device__ __nv_bfloat16 g_Qlo[(size_t)cB * cNH * cS * cD];
__device__ __nv_bfloat16 g_Khi[(size_t)cB * cNH * cS * cD];
__device__ __nv_bfloat16 g_Klo[(size_t)cB * cNH * cS * cD];
__device__ __nv_bfloat16 g_Vhi[(size_t)cB * cNH * cS * cD];
__device__ __nv_bfloat16 g_Vlo[(size_t)cB * cNH * cS * cD];
__device__ __nv_bfloat16 g_Oh [(size_t)cM * cH];
__device__ __nv_bfloat16 g_Ol [(size_t)cM * cH];
__device__ __nv_bfloat16 g_Xh3[3][(size_t)cM * cH];
__device__ __nv_bfloat16 g_Xl3[3][(size_t)cM * cH];
__device__ __nv_bfloat16 g_Wh4[4][(size_t)cH * cH];
__device__ __nv_bfloat16 g_Wl4[4][(size_t)cH * cH];
// bit-packed mask: [b*cS + q][64 words of 32 key-bits]
__device__ uint32_t g_Mb[(size_t)cB * cS * (cS / 32)];

// ---------------------------------------------------------------------------
// Helpers
// ---------------------------------------------------------------------------
__device__ __forceinline__ uint32_t smem_u32(const void* p) {
    uint32_t a;
    asm("{ .reg .u64 t; cvta.to.shared.u64 t, %1; cvt.u32.u64 %0, t; }" : "=r"(a) : "l"(p));
    return a;
}
__device__ __forceinline__ void ldsm_x4(uint32_t* r, uint32_t addr) {
    asm volatile("ldmatrix.sync.aligned.m8n8.x4.shared.b16 {%0,%1,%2,%3}, [%4];"
                 : "=r"(r[0]), "=r"(r[1]), "=r"(r[2]), "=r"(r[3]) : "r"(addr));
}
__device__ __forceinline__ void ldsm_x4_t(uint32_t* r, uint32_t addr) {
    asm volatile("ldmatrix.sync.aligned.m8n8.x4.trans.shared.b16 {%0,%1,%2,%3}, [%4];"
                 : "=r"(r[0]), "=r"(r[1]), "=r"(r[2]), "=r"(r[3]) : "r"(addr));
}
__device__ __forceinline__ void mma_bf16(float* d, const uint32_t* a, const uint32_t* b) {
    asm volatile(
        "mma.sync.aligned.m16n8k16.row.col.f32.bf16.bf16.f32 "
        "{%0,%1,%2,%3}, {%4,%5,%6,%7}, {%8,%9}, {%0,%1,%2,%3};"
        : "+f"(d[0]), "+f"(d[1]), "+f"(d[2]), "+f"(d[3])
        : "r"(a[0]), "r"(a[1]), "r"(a[2]), "r"(a[3]), "r"(b[0]), "r"(b[1]));
}
__device__ __forceinline__ uint32_t sw64(uint32_t off) {
    return off ^ ((off >> 3) & 0x30);
}
#define SW128(off) ((off) ^ (((off) >> 3) & 0x70))

__device__ __forceinline__ uint32_t packbf(float lo, float hi) {
    uint32_t d;
    asm("cvt.rn.bf16x2.f32 %0, %1, %2;" : "=r"(d) : "f"(hi), "f"(lo));
    return d;
}
__device__ __forceinline__ float bflo(uint32_t v) { return __uint_as_float(v << 16); }
__device__ __forceinline__ float bfhi(uint32_t v) { return __uint_as_float(v & 0xffff0000u); }

__device__ __forceinline__ void cpa16(uint32_t saddr, const void* g) {
    asm volatile("cp.async.cg.shared.global [%0], [%1], 16;" :: "r"(saddr), "l"(g) : "memory");
}
#define CP_COMMIT() asm volatile("cp.async.commit_group;" ::: "memory")
#define CP_WAIT(n)  asm volatile("cp.async.wait_group %0;" :: "n"(n) : "memory")

// ---------------------------------------------------------------------------
// Mask bitpack: one warp packs one 32-key word per iteration (ballot).
// ---------------------------------------------------------------------------
__global__ void maskpack_kernel(const int* __restrict__ mask)
{
    int warp = (blockIdx.x * blockDim.x + threadIdx.x) >> 5;
    int lane = threadIdx.x & 31;
    // total words = cB*cS*(cS/32) = 262144
    int m = mask[(size_t)warp * 32 + lane];
    uint32_t bits = __ballot_sync(0xffffffffu, m != 0);
    if (lane == 0) g_Mb[warp] = bits;
}

// ---------------------------------------------------------------------------
// Fused splits
// ---------------------------------------------------------------------------
__device__ __forceinline__ void split_one(const float* __restrict__ x,
                                          __nv_bfloat16* __restrict__ hi,
                                          __nv_bfloat16* __restrict__ lo, int i)
{
    float4 v = ((const float4*)x)[i];
    uint32_t h0 = packbf(v.x, v.y);
    uint32_t h1 = packbf(v.z, v.w);
    ((uint32_t*)hi)[i * 2 + 0] = h0;
    ((uint32_t*)hi)[i * 2 + 1] = h1;
    ((uint32_t*)lo)[i * 2 + 0] = packbf(v.x - bflo(h0), v.y - bfhi(h0));
    ((uint32_t*)lo)[i * 2 + 1] = packbf(v.z - bflo(h1), v.w - bfhi(h1));
}

__global__ void split3x_kernel(const float* __restrict__ q, const float* __restrict__ k,
                               const float* __restrict__ v, int n4)
{
    int i = blockIdx.x * blockDim.x + threadIdx.x;
    if (i >= n4) return;
    int z = blockIdx.y;
    const float* x = (z == 0) ? q : (z == 1) ? k : v;
    split_one(x, g_Xh3[z], g_Xl3[z], i);
}

__global__ void split4w_kernel(const float* __restrict__ Wq, const float* __restrict__ Wk,
                               const float* __restrict__ Wv, const float* __restrict__ Wo, int n4)
{
    int i = blockIdx.x * blockDim.x + threadIdx.x;
    if (i >= n4) return;
    int z = blockIdx.y;
    const float* w = (z == 0) ? Wq : (z == 1) ? Wk : (z == 2) ? Wv : Wo;
    split_one(w, g_Wh4[z], g_Wl4[z], i);
}

// ---------------------------------------------------------------------------
// HMMA split-bf16 GEMM body (round-10/11 proven version).
// ---------------------------------------------------------------------------
constexpr int BM = 128, BN = 128, BK = 32;
constexpr int GEMM_SMEM = 2 * 32768;

__device__ __forceinline__ void gemm_body(
    const __nv_bfloat16* __restrict__ Ah, const __nv_bfloat16* __restrict__ Al,
    const __nv_bfloat16* __restrict__ Bh, const __nv_bfloat16* __restrict__ Bl,
    const float* __restrict__ bias, float* __restrict__ outf,
    __nv_bfloat16* __restrict__ outh, __nv_bfloat16* __restrict__ outl,
    int headsplit, int m0, int n0, char* smem)
{
    const uint32_t sbase = smem_u32(smem);
    const int tid  = threadIdx.x;
    const int lane = tid & 31;
    const int wid  = tid >> 5;
    const int wm   = (wid & 1) * 64;
    const int wn   = (wid >> 1) * 32;

    uint32_t offA[4], offAl[4], offB[2], offBl[2];
#pragma unroll
    for (int mf = 0; mf < 4; mf++) {
        int row  = wm + mf * 16 + (lane & 15);
        int koff = ((lane >> 4) & 1) * 16;
        uint32_t off = sw64(row * 64 + koff);
        offA [mf] = off;
        offAl[mf] = 8192 + off;
    }
#pragma unroll
    for (int p = 0; p < 2; p++) {
        int row  = wn + p * 16 + ((lane & 16) >> 1) + (lane & 7);
        int koff = ((lane & 8) >> 3) * 16;
        uint32_t off = sw64(row * 64 + koff);
        offB [p] = 16384 + off;
        offBl[p] = 24576 + off;
    }

    const int crow = tid >> 2;
    const int cq   = tid & 3;
    const uint32_t so0 = sw64(crow * 64 + cq * 16);
    const uint32_t so1 = sw64((crow + 64) * 64 + cq * 16);

    auto issue = [&](int t) {
        uint32_t sd = sbase + (t & 1) * 32768;
        int kt = t * BK;
        size_t ga0 = ((size_t)(m0 + crow) << 10) + kt + cq * 8;
        size_t ga1 = ((size_t)(m0 + crow + 64) << 10) + kt + cq * 8;
        size_t gb0 = ((size_t)(n0 + crow) << 10) + kt + cq * 8;
        size_t gb1 = ((size_t)(n0 + crow + 64) << 10) + kt + cq * 8;
        cpa16(sd + so0,          Ah + ga0);
        cpa16(sd + so1,          Ah + ga1);
        cpa16(sd + 8192  + so0,  Al + ga0);
        cpa16(sd + 8192  + so1,  Al + ga1);
        cpa16(sd + 16384 + so0,  Bh + gb0);
        cpa16(sd + 16384 + so1,  Bh + gb1);
        cpa16(sd + 24576 + so0,  Bl + gb0);
        cpa16(sd + 24576 + so1,  Bl + gb1);
        CP_COMMIT();
    };

    float acc[4][4][4];
#pragma unroll
    for (int mf = 0; mf < 4; mf++)
#pragma unroll
        for (int nf = 0; nf < 4; nf++)
#pragma unroll
            for (int r = 0; r < 4; r++) acc[mf][nf][r] = 0.0f;

    issue(0);

    constexpr int NT = cH / BK;
    for (int t = 0; t < NT; t++) {
        if (t + 1 < NT) {
            issue(t + 1);
            CP_WAIT(1);
        } else {
            CP_WAIT(0);
        }
        __syncthreads();

        const uint32_t sd = sbase + (t & 1) * 32768;
#pragma unroll
        for (int s = 0; s < 2; s++) {
            const uint32_t xa = s * 32;
            uint32_t ah[4][4], al[4][4], bh[2][4], bl[2][4];
#pragma unroll
            for (int mf = 0; mf < 4; mf++) {
                ldsm_x4(ah[mf], sd + (offA [mf] ^ xa));
                ldsm_x4(al[mf], sd + (offAl[mf] ^ xa));
            }
#pragma unroll
            for (int p = 0; p < 2; p++) {
                ldsm_x4(bh[p], sd + (offB [p] ^ xa));
                ldsm_x4(bl[p], sd + (offBl[p] ^ xa));
            }
#pragma unroll
            for (int mf = 0; mf < 4; mf++)
#pragma unroll
                for (int nf = 0; nf < 4; nf++) {
                    const uint32_t* bhp = &bh[nf >> 1][(nf & 1) * 2];
                    const uint32_t* blp = &bl[nf >> 1][(nf & 1) * 2];
                    mma_bf16(acc[mf][nf], ah[mf], bhp);
                    mma_bf16(acc[mf][nf], al[mf], bhp);
                    mma_bf16(acc[mf][nf], ah[mf], blp);
                }
        }
        __syncthreads();
    }

#pragma unroll
    for (int mf = 0; mf < 4; mf++) {
        int m1 = m0 + wm + mf * 16 + (lane >> 2);
#pragma unroll
        for (int nf = 0; nf < 4; nf++) {
            int n = n0 + wn + nf * 8 + (lane & 3) * 2;
            float2 bv = *(const float2*)(bias + n);
            float* a = acc[mf][nf];
            float c00 = a[0] + bv.x, c01 = a[1] + bv.y;
            float c10 = a[2] + bv.x, c11 = a[3] + bv.y;
            if (headsplit) {
                int h = n >> 6, dd = n & 63;
                int bb1 = m1 >> 11, s1 = m1 & 2047;
                int m2 = m1 + 8;
                int bb2 = m2 >> 11, s2 = m2 & 2047;
                size_t i1 = (((size_t)(bb1 * cNH + h)) * cS + s1) * cD + dd;
                size_t i2 = (((size_t)(bb2 * cNH + h)) * cS + s2) * cD + dd;
                uint32_t h0 = packbf(c00, c01);
                uint32_t h1 = packbf(c10, c11);
                *(uint32_t*)((char*)outh + i1 * 2) = h0;
                *(uint32_t*)((char*)outh + i2 * 2) = h1;
                *(uint32_t*)((char*)outl + i1 * 2) = packbf(c00 - bflo(h0), c01 - bfhi(h0));
                *(uint32_t*)((char*)outl + i2 * 2) = packbf(c10 - bflo(h1), c11 - bfhi(h1));
            } else {
                *(float2*)(outf + (size_t)m1 * cH + n)       = make_float2(c00, c01);
                *(float2*)(outf + (size_t)(m1 + 8) * cH + n) = make_float2(c10, c11);
            }
        }
    }
}

__global__ __launch_bounds__(256, 1) void qkv_gemm_kernel(
    const float* __restrict__ bq, const float* __restrict__ bk, const float* __restrict__ bv)
{
    extern __shared__ char smem[];
    const int z = blockIdx.z;
    const float* bias = (z == 0) ? bq : (z == 1) ? bk : bv;
    __nv_bfloat16* outh = (z == 0) ? g_Qhi : (z == 1) ? g_Khi : g_Vhi;
    __nv_bfloat16* outl = (z == 0) ? g_Qlo : (z == 1) ? g_Klo : g_Vlo;
    gemm_body(g_Xh3[z], g_Xl3[z], g_Wh4[z], g_Wl4[z], bias,
              nullptr, outh, outl, 1, blockIdx.y * BM, blockIdx.x * BN, smem);
}

__global__ __launch_bounds__(256, 1) void o_gemm_kernel(
    const float* __restrict__ bo, float* __restrict__ out)
{
    extern __shared__ char smem[];
    gemm_body(g_Oh, g_Ol, g_Wh4[3], g_Wl4[3], bo,
              out, nullptr, nullptr, 0, blockIdx.y * BM, blockIdx.x * BN, smem);
}

// ---------------------------------------------------------------------------
// Flash attention v7 = round-11 attn4 numerics + bit-packed mask.
// 128 threads / 4 warps / 64 q-rows, 2 CTA/SM, fixed-max softmax,
// deferred l-reduction, full split Q/K (3-pass S) and P/V (3-pass PV).
// ---------------------------------------------------------------------------
constexpr int ATTN_SMEM = 2 * 32768;

__global__ __launch_bounds__(128, 2) void attn7_kernel()
{
    extern __shared__ char smc[];
    const uint32_t sb = smem_u32(smc);

    const int tid  = threadIdx.x;
    const int lane = tid & 31;
    const int wid  = tid >> 5;
    const int wm   = wid * 16;
    const int bh   = blockIdx.y;
    const int b    = bh >> 4;
    const int h    = bh & 15;
    const int q0   = blockIdx.x * 64;
    const size_t qkv = (size_t)bh * cS * cD;

    // ---- stage Q: Qhi @0, Qlo @8192 ----
#pragma unroll
    for (int i = 0; i < 4; i++) {
        int u = tid + i * 128;
        int row = u >> 3, un = u & 7;
        uint32_t so = SW128(row * 128 + un * 16);
        size_t g = qkv + (size_t)(q0 + row) * cD + un * 8;
        *(uint4*)(smc + so)        = *(const uint4*)(g_Qhi + g);
        *(uint4*)(smc + 8192 + so) = *(const uint4*)(g_Qlo + g);
    }
    __syncthreads();

    const int qrow = wm + ((lane >> 3) & 1) * 8 + (lane & 7);
    const uint32_t qc   = ((lane >> 4) & 1) * 16;
    const uint32_t qxr  = (qrow & 7) << 4;
    const uint32_t qoff = qrow * 128 + qc;
    uint32_t qh[4][4], ql[4][4];
#pragma unroll
    for (int kf = 0; kf < 4; kf++) {
        uint32_t a = (qoff + kf * 32) ^ qxr;
        ldsm_x4(qh[kf], sb + a);
        ldsm_x4(ql[kf], sb + 8192 + a);
    }
    __syncthreads();

    const int krow_l = ((lane >> 4) & 1) * 8 + (lane & 7);
    const uint32_t kc    = ((lane >> 3) & 1) * 16;
    const uint32_t kxr   = (krow_l & 7) << 4;
    const uint32_t kbase = krow_l * 128 + kc;

    const int vrow_l = ((lane >> 3) & 1) * 8 + (lane & 7);
    const uint32_t vc    = ((lane >> 4) & 1) * 16;
    const uint32_t vxr   = (vrow_l & 7) << 4;
    const uint32_t vbase = vrow_l * 128 + vc;

    float o[8][4];
#pragma unroll
    for (int nf = 0; nf < 8; nf++)
#pragma unroll
        for (int r = 0; r < 4; r++) o[nf][r] = 0.0f;
    float l0 = 0.0f, l1 = 0.0f;
    const float PMASK = __expf(1e-9f - 8.0f);

    auto stage = [&](int t) {
        uint32_t sd = sb + (t & 1) * 32768;
        const int kt = t * 64;
#pragma unroll
        for (int i = 0; i < 4; i++) {
            int u = tid + i * 128;
            int row = u >> 3, un = u & 7;
            uint32_t so = SW128(row * 128 + un * 16);
            size_t g = (qkv + (size_t)(kt + row) * cD + un * 8) * 2;
            cpa16(sd + so,          (const char*)g_Khi + g);
            cpa16(sd + 8192 + so,   (const char*)g_Klo + g);
            cpa16(sd + 16384 + so,  (const char*)g_Vhi + g);
            cpa16(sd + 24576 + so,  (const char*)g_Vlo + g);
        }
        CP_COMMIT();
    };

    stage(0);

    // bit-packed mask pointers: row -> 64 words; per tile need words [t*2, t*2+1]
    const uint32_t* mb0 = g_Mb + ((size_t)b * cS + (q0 + wm + (lane >> 2))) * (cS / 32);
    const uint32_t* mb1 = mb0 + (size_t)8 * (cS / 32);
    const int kb = (lane & 3) * 2;   // key bit base within 8-bit group

    for (int t = 0; t < cS / 64; t++) {
        if (t + 1 < cS / 64) {
            stage(t + 1);
            CP_WAIT(1);
        } else {
            CP_WAIT(0);
        }
        __syncthreads();

        const uint32_t sK = sb + (t & 1) * 32768;
        const uint32_t sV = sK + 16384;

        // ---- S = Q K^T (split, fp32 accum) ----
        float s[8][4];
#pragma unroll
        for (int nf = 0; nf < 8; nf++)
#pragma unroll
            for (int r = 0; r < 4; r++) s[nf][r] = 0.0f;

#pragma unroll
        for (int kf = 0; kf < 4; kf++) {
#pragma unroll
            for (int nb = 0; nb < 4; nb++) {
                uint32_t rh[4], rl[4];
                uint32_t a = (kbase + nb * 2048 + kf * 32) ^ kxr;
                ldsm_x4(rh, sK + a);
                ldsm_x4(rl, sK + 8192 + a);
                mma_bf16(s[2 * nb],     qh[kf], rh);
                mma_bf16(s[2 * nb],     ql[kf], rh);
                mma_bf16(s[2 * nb],     qh[kf], rl);
                mma_bf16(s[2 * nb + 1], qh[kf], rh + 2);
                mma_bf16(s[2 * nb + 1], ql[kf], rh + 2);
                mma_bf16(s[2 * nb + 1], qh[kf], rl + 2);
            }
        }

        // ---- bit-mask + fixed-max exp ----
        uint2 w0 = *(const uint2*)(mb0 + t * 2);
        uint2 w1 = *(const uint2*)(mb1 + t * 2);
#pragma unroll
        for (int nf = 0; nf < 8; nf++) {
            uint32_t ww0 = (nf < 4) ? w0.x : w0.y;
            uint32_t ww1 = (nf < 4) ? w1.x : w1.y;
            int bit = kb + (nf & 3) * 8;
            s[nf][0] = !((ww0 >> bit) & 1)       ? PMASK : __expf(fmaf(s[nf][0], 0.125f, -8.0f));
            s[nf][1] = !((ww0 >> (bit + 1)) & 1) ? PMASK : __expf(fmaf(s[nf][1], 0.125f, -8.0f));
            s[nf][2] = !((ww1 >> bit) & 1)       ? PMASK : __expf(fmaf(s[nf][2], 0.125f, -8.0f));
            s[nf][3] = !((ww1 >> (bit + 1)) & 1) ? PMASK : __expf(fmaf(s[nf][3], 0.125f, -8.0f));
            l0 += s[nf][0] + s[nf][1];
            l1 += s[nf][2] + s[nf][3];
        }

        // ---- O += P V (split) ----
#pragma unroll
        for (int kf = 0; kf < 4; kf++) {
            uint32_t ph[4], pl[4];
            ph[0] = packbf(s[2 * kf][0],     s[2 * kf][1]);
            ph[1] = packbf(s[2 * kf][2],     s[2 * kf][3]);
            ph[2] = packbf(s[2 * kf + 1][0], s[2 * kf + 1][1]);
            ph[3] = packbf(s[2 * kf + 1][2], s[2 * kf + 1][3]);
            pl[0] = packbf(s[2 * kf][0]     - bflo(ph[0]), s[2 * kf][1]     - bfhi(ph[0]));
            pl[1] = packbf(s[2 * kf][2]     - bflo(ph[1]), s[2 * kf][3]     - bfhi(ph[1]));
            pl[2] = packbf(s[2 * kf + 1][0] - bflo(ph[2]), s[2 * kf + 1][1] - bfhi(ph[2]));
            pl[3] = packbf(s[2 * kf + 1][2] - bflo(ph[3]), s[2 * kf + 1][3] - bfhi(ph[3]));
#pragma unroll
            for (int db = 0; db < 4; db++) {
                uint32_t vh[4], vl[4];
                uint32_t a = (vbase + kf * 2048 + db * 32) ^ vxr;
                ldsm_x4_t(vh, sV + a);
                ldsm_x4_t(vl, sV + 8192 + a);
                mma_bf16(o[2 * db],     ph, vh);
                mma_bf16(o[2 * db],     pl, vh);
                mma_bf16(o[2 * db],     ph, vl);
                mma_bf16(o[2 * db + 1], ph, vh + 2);
                mma_bf16(o[2 * db + 1], pl, vh + 2);
                mma_bf16(o[2 * db + 1], ph, vl + 2);
            }
        }
        __syncthreads();
    }

    // ---- final l reduction + normalize + write hi/lo bf16 ----
    l0 += __shfl_xor_sync(0xffffffffu, l0, 1);
    l0 += __shfl_xor_sync(0xffffffffu, l0, 2);
    l1 += __shfl_xor_sync(0xffffffffu, l1, 1);
    l1 += __shfl_xor_sync(0xffffffffu, l1, 2);
    float inv0 = 1.0f / l0, inv1 = 1.0f / l1;
    int row0 = q0 + wm + (lane >> 2);
#pragma unroll
    for (int nf = 0; nf < 8; nf++) {
        int dcol = h * cD + nf * 8 + (lane & 3) * 2;
        size_t i1 = ((size_t)b * cS + row0) * cH + dcol;
        size_t i2 = i1 + (size_t)8 * cH;
        float f0 = o[nf][0] * inv0, f1 = o[nf][1] * inv0;
        float f2 = o[nf][2] * inv1, f3 = o[nf][3] * inv1;
        uint32_t h0 = packbf(f0, f1);
        uint32_t h1 = packbf(f2, f3);
        *(uint32_t*)((char*)g_Oh + i1 * 2) = h0;
        *(uint32_t*)((char*)g_Oh + i2 * 2) = h1;
        *(uint32_t*)((char*)g_Ol + i1 * 2) = packbf(f0 - bflo(h0), f1 - bfhi(h0));
        *(uint32_t*)((char*)g_Ol + i2 * 2) = packbf(f2 - bflo(h1), f3 - bfhi(h1));
    }
}

// ---------------------------------------------------------------------------
extern "C" void kernel_launch(void* const* d_in, const int* in_sizes, int n_in,
                              void* d_out, int out_size)
{
    const float* q    = (const float*)d_in[0];
    const float* k    = (const float*)d_in[1];
    const float* v    = (const float*)d_in[2];
    const int*   mask = (const int*)  d_in[3];
    const float* Wq   = (const float*)d_in[4];
    const float* bq   = (const float*)d_in[5];
    const float* Wk   = (const float*)d_in[6];
    const float* bk   = (const float*)d_in[7];
    const float* Wv   = (const float*)d_in[8];
    const float* bv   = (const float*)d_in[9];
    const float* Wo   = (const float*)d_in[10];
    const float* bo   = (const float*)d_in[11];

    cudaFuncSetAttribute(qkv_gemm_kernel,
                         cudaFuncAttributeMaxDynamicSharedMemorySize, GEMM_SMEM);
    cudaFuncSetAttribute(o_gemm_kernel,
                         cudaFuncAttributeMaxDynamicSharedMemorySize, GEMM_SMEM);
    cudaFuncSetAttribute(attn7_kernel,
                         cudaFuncAttributeMaxDynamicSharedMemorySize, ATTN_SMEM);

    const int nX4 = cM * cH / 4;
    const int nW4 = cH * cH / 4;

    split3x_kernel<<<dim3(nX4 / 256, 3), 256>>>(q, k, v, nX4);
    split4w_kernel<<<dim3(nW4 / 256, 4), 256>>>(Wq, Wk, Wv, Wo, nW4);
    // pack mask bits: cB*cS*cS/32 words, one warp-word per 32 threads
    maskpack_kernel<<<(cB * cS * (cS / 32)) / 8, 256>>>(mask);

    qkv_gemm_kernel<<<dim3(cH / BN, cM / BM, 3), 256, GEMM_SMEM>>>(bq, bk, bv);

    attn7_kernel<<<dim3(cS / 64, cB * cNH), 128, ATTN_SMEM>>>();

    o_gemm_kernel<<<dim3(cH / BN, cM / BM), 256, GEMM_SMEM>>>(bo, (float*)d_out);
}

// round 17
// speedup vs baseline: 1.2793x; 1.2793x over previous
#include <cuda_runtime.h>
#include <cuda_bf16.h>
#include <cuda_fp16.h>
#include <stdint.h>
#include <math.h>

// Problem constants
constexpr int cB  = 2;
constexpr int cS  = 2048;
constexpr int cH  = 1024;
constexpr int cNH = 16;
constexpr int cD  = 64;
constexpr int cM  = cB * cS;   // 4096

// fp16 attention operands (written by projection GEMM epilogue)
__device__ __half g_Qh16[(size_t)cB * cNH * cS * cD];
__device__ __half g_Kh16[(size_t)cB * cNH * cS * cD];
__device__ __half g_Vh16[(size_t)cB * cNH * cS * cD];
// bf16 split scratch for GEMMs (numerics proven at 2.2e-5)
__device__ __nv_bfloat16 g_Oh [(size_t)cM * cH];
__device__ __nv_bfloat16 g_Ol [(size_t)cM * cH];
__device__ __nv_bfloat16 g_Xh3[3][(size_t)cM * cH];
__device__ __nv_bfloat16 g_Xl3[3][(size_t)cM * cH];
__device__ __nv_bfloat16 g_Wh4[4][(size_t)cH * cH];
__device__ __nv_bfloat16 g_Wl4[4][(size_t)cH * cH];
// bit-packed mask
__device__ uint32_t g_Mb[(size_t)cB * cS * (cS / 32)];

// ---------------------------------------------------------------------------
// Helpers
// ---------------------------------------------------------------------------
__device__ __forceinline__ uint32_t smem_u32(const void* p) {
    uint32_t a;
    asm("{ .reg .u64 t; cvta.to.shared.u64 t, %1; cvt.u32.u64 %0, t; }" : "=r"(a) : "l"(p));
    return a;
}
__device__ __forceinline__ void ldsm_x4(uint32_t* r, uint32_t addr) {
    asm volatile("ldmatrix.sync.aligned.m8n8.x4.shared.b16 {%0,%1,%2,%3}, [%4];"
                 : "=r"(r[0]), "=r"(r[1]), "=r"(r[2]), "=r"(r[3]) : "r"(addr));
}
__device__ __forceinline__ void ldsm_x4_t(uint32_t* r, uint32_t addr) {
    asm volatile("ldmatrix.sync.aligned.m8n8.x4.trans.shared.b16 {%0,%1,%2,%3}, [%4];"
                 : "=r"(r[0]), "=r"(r[1]), "=r"(r[2]), "=r"(r[3]) : "r"(addr));
}
__device__ __forceinline__ void mma_bf16(float* d, const uint32_t* a, const uint32_t* b) {
    asm volatile(
        "mma.sync.aligned.m16n8k16.row.col.f32.bf16.bf16.f32 "
        "{%0,%1,%2,%3}, {%4,%5,%6,%7}, {%8,%9}, {%0,%1,%2,%3};"
        : "+f"(d[0]), "+f"(d[1]), "+f"(d[2]), "+f"(d[3])
        : "r"(a[0]), "r"(a[1]), "r"(a[2]), "r"(a[3]), "r"(b[0]), "r"(b[1]));
}
__device__ __forceinline__ void mma_fp16(float* d, const uint32_t* a, const uint32_t* b) {
    asm volatile(
        "mma.sync.aligned.m16n8k16.row.col.f32.f16.f16.f32 "
        "{%0,%1,%2,%3}, {%4,%5,%6,%7}, {%8,%9}, {%0,%1,%2,%3};"
        : "+f"(d[0]), "+f"(d[1]), "+f"(d[2]), "+f"(d[3])
        : "r"(a[0]), "r"(a[1]), "r"(a[2]), "r"(a[3]), "r"(b[0]), "r"(b[1]));
}
__device__ __forceinline__ uint32_t sw64(uint32_t off) {
    return off ^ ((off >> 3) & 0x30);
}
#define SW128(off) ((off) ^ (((off) >> 3) & 0x70))

__device__ __forceinline__ uint32_t packbf(float lo, float hi) {
    uint32_t d;
    asm("cvt.rn.bf16x2.f32 %0, %1, %2;" : "=r"(d) : "f"(hi), "f"(lo));
    return d;
}
__device__ __forceinline__ float bflo(uint32_t v) { return __uint_as_float(v << 16); }
__device__ __forceinline__ float bfhi(uint32_t v) { return __uint_as_float(v & 0xffff0000u); }

__device__ __forceinline__ uint32_t packf16(float lo, float hi) {
    uint32_t d;
    asm("cvt.rn.f16x2.f32 %0, %1, %2;" : "=r"(d) : "f"(hi), "f"(lo));
    return d;
}
__device__ __forceinline__ float f16lo(uint32_t v) {
    return __half2float(__ushort_as_half((unsigned short)(v & 0xffffu)));
}
__device__ __forceinline__ float f16hi(uint32_t v) {
    return __half2float(__ushort_as_half((unsigned short)(v >> 16)));
}

__device__ __forceinline__ void cpa16(uint32_t saddr, const void* g) {
    asm volatile("cp.async.cg.shared.global [%0], [%1], 16;" :: "r"(saddr), "l"(g) : "memory");
}
#define CP_COMMIT() asm volatile("cp.async.commit_group;" ::: "memory")
#define CP_WAIT(n)  asm volatile("cp.async.wait_group %0;" :: "n"(n) : "memory")

// ---------------------------------------------------------------------------
// Mask bitpack
// ---------------------------------------------------------------------------
__global__ void maskpack_kernel(const int* __restrict__ mask)
{
    int warp = (blockIdx.x * blockDim.x + threadIdx.x) >> 5;
    int lane = threadIdx.x & 31;
    int m = mask[(size_t)warp * 32 + lane];
    uint32_t bits = __ballot_sync(0xffffffffu, m != 0);
    if (lane == 0) g_Mb[warp] = bits;
}

// ---------------------------------------------------------------------------
// Fused splits (fp32 -> bf16 hi/lo, GEMM inputs)
// ---------------------------------------------------------------------------
__device__ __forceinline__ void split_one(const float* __restrict__ x,
                                          __nv_bfloat16* __restrict__ hi,
                                          __nv_bfloat16* __restrict__ lo, int i)
{
    float4 v = ((const float4*)x)[i];
    uint32_t h0 = packbf(v.x, v.y);
    uint32_t h1 = packbf(v.z, v.w);
    ((uint32_t*)hi)[i * 2 + 0] = h0;
    ((uint32_t*)hi)[i * 2 + 1] = h1;
    ((uint32_t*)lo)[i * 2 + 0] = packbf(v.x - bflo(h0), v.y - bfhi(h0));
    ((uint32_t*)lo)[i * 2 + 1] = packbf(v.z - bflo(h1), v.w - bfhi(h1));
}

__global__ void split3x_kernel(const float* __restrict__ q, const float* __restrict__ k,
                               const float* __restrict__ v, int n4)
{
    int i = blockIdx.x * blockDim.x + threadIdx.x;
    if (i >= n4) return;
    int z = blockIdx.y;
    const float* x = (z == 0) ? q : (z == 1) ? k : v;
    split_one(x, g_Xh3[z], g_Xl3[z], i);
}

__global__ void split4w_kernel(const float* __restrict__ Wq, const float* __restrict__ Wk,
                               const float* __restrict__ Wv, const float* __restrict__ Wo, int n4)
{
    int i = blockIdx.x * blockDim.x + threadIdx.x;
    if (i >= n4) return;
    int z = blockIdx.y;
    const float* w = (z == 0) ? Wq : (z == 1) ? Wk : (z == 2) ? Wv : Wo;
    split_one(w, g_Wh4[z], g_Wl4[z], i);
}

// ---------------------------------------------------------------------------
// HMMA split-bf16 GEMM body. headsplit=1 writes fp16 single to out16.
// ---------------------------------------------------------------------------
constexpr int BM = 128, BN = 128, BK = 32;
constexpr int GEMM_SMEM = 2 * 32768;

__device__ __forceinline__ void gemm_body(
    const __nv_bfloat16* __restrict__ Ah, const __nv_bfloat16* __restrict__ Al,
    const __nv_bfloat16* __restrict__ Bh, const __nv_bfloat16* __restrict__ Bl,
    const float* __restrict__ bias, float* __restrict__ outf,
    __half* __restrict__ out16, int headsplit, int m0, int n0, char* smem)
{
    const uint32_t sbase = smem_u32(smem);
    const int tid  = threadIdx.x;
    const int lane = tid & 31;
    const int wid  = tid >> 5;
    const int wm   = (wid & 1) * 64;
    const int wn   = (wid >> 1) * 32;

    uint32_t offA[4], offAl[4], offB[2], offBl[2];
#pragma unroll
    for (int mf = 0; mf < 4; mf++) {
        int row  = wm + mf * 16 + (lane & 15);
        int koff = ((lane >> 4) & 1) * 16;
        uint32_t off = sw64(row * 64 + koff);
        offA [mf] = off;
        offAl[mf] = 8192 + off;
    }
#pragma unroll
    for (int p = 0; p < 2; p++) {
        int row  = wn + p * 16 + ((lane & 16) >> 1) + (lane & 7);
        int koff = ((lane & 8) >> 3) * 16;
        uint32_t off = sw64(row * 64 + koff);
        offB [p] = 16384 + off;
        offBl[p] = 24576 + off;
    }

    const int crow = tid >> 2;
    const int cq   = tid & 3;
    const uint32_t so0 = sw64(crow * 64 + cq * 16);
    const uint32_t so1 = sw64((crow + 64) * 64 + cq * 16);

    auto issue = [&](int t) {
        uint32_t sd = sbase + (t & 1) * 32768;
        int kt = t * BK;
        size_t ga0 = ((size_t)(m0 + crow) << 10) + kt + cq * 8;
        size_t ga1 = ((size_t)(m0 + crow + 64) << 10) + kt + cq * 8;
        size_t gb0 = ((size_t)(n0 + crow) << 10) + kt + cq * 8;
        size_t gb1 = ((size_t)(n0 + crow + 64) << 10) + kt + cq * 8;
        cpa16(sd + so0,          Ah + ga0);
        cpa16(sd + so1,          Ah + ga1);
        cpa16(sd + 8192  + so0,  Al + ga0);
        cpa16(sd + 8192  + so1,  Al + ga1);
        cpa16(sd + 16384 + so0,  Bh + gb0);
        cpa16(sd + 16384 + so1,  Bh + gb1);
        cpa16(sd + 24576 + so0,  Bl + gb0);
        cpa16(sd + 24576 + so1,  Bl + gb1);
        CP_COMMIT();
    };

    float acc[4][4][4];
#pragma unroll
    for (int mf = 0; mf < 4; mf++)
#pragma unroll
        for (int nf = 0; nf < 4; nf++)
#pragma unroll
            for (int r = 0; r < 4; r++) acc[mf][nf][r] = 0.0f;

    issue(0);

    constexpr int NT = cH / BK;
    for (int t = 0; t < NT; t++) {
        if (t + 1 < NT) {
            issue(t + 1);
            CP_WAIT(1);
        } else {
            CP_WAIT(0);
        }
        __syncthreads();

        const uint32_t sd = sbase + (t & 1) * 32768;
#pragma unroll
        for (int s = 0; s < 2; s++) {
            const uint32_t xa = s * 32;
            uint32_t ah[4][4], al[4][4], bh[2][4], bl[2][4];
#pragma unroll
            for (int mf = 0; mf < 4; mf++) {
                ldsm_x4(ah[mf], sd + (offA [mf] ^ xa));
                ldsm_x4(al[mf], sd + (offAl[mf] ^ xa));
            }
#pragma unroll
            for (int p = 0; p < 2; p++) {
                ldsm_x4(bh[p], sd + (offB [p] ^ xa));
                ldsm_x4(bl[p], sd + (offBl[p] ^ xa));
            }
#pragma unroll
            for (int mf = 0; mf < 4; mf++)
#pragma unroll
                for (int nf = 0; nf < 4; nf++) {
                    const uint32_t* bhp = &bh[nf >> 1][(nf & 1) * 2];
                    const uint32_t* blp = &bl[nf >> 1][(nf & 1) * 2];
                    mma_bf16(acc[mf][nf], ah[mf], bhp);
                    mma_bf16(acc[mf][nf], al[mf], bhp);
                    mma_bf16(acc[mf][nf], ah[mf], blp);
                }
        }
        __syncthreads();
    }

#pragma unroll
    for (int mf = 0; mf < 4; mf++) {
        int m1 = m0 + wm + mf * 16 + (lane >> 2);
#pragma unroll
        for (int nf = 0; nf < 4; nf++) {
            int n = n0 + wn + nf * 8 + (lane & 3) * 2;
            float2 bv = *(const float2*)(bias + n);
            float* a = acc[mf][nf];
            float c00 = a[0] + bv.x, c01 = a[1] + bv.y;
            float c10 = a[2] + bv.x, c11 = a[3] + bv.y;
            if (headsplit) {
                int h = n >> 6, dd = n & 63;
                int bb1 = m1 >> 11, s1 = m1 & 2047;
                int m2 = m1 + 8;
                int bb2 = m2 >> 11, s2 = m2 & 2047;
                size_t i1 = (((size_t)(bb1 * cNH + h)) * cS + s1) * cD + dd;
                size_t i2 = (((size_t)(bb2 * cNH + h)) * cS + s2) * cD + dd;
                *(uint32_t*)((char*)out16 + i1 * 2) = packf16(c00, c01);
                *(uint32_t*)((char*)out16 + i2 * 2) = packf16(c10, c11);
            } else {
                *(float2*)(outf + (size_t)m1 * cH + n)       = make_float2(c00, c01);
                *(float2*)(outf + (size_t)(m1 + 8) * cH + n) = make_float2(c10, c11);
            }
        }
    }
}

__global__ __launch_bounds__(256, 1) void qkv_gemm_kernel(
    const float* __restrict__ bq, const float* __restrict__ bk, const float* __restrict__ bv)
{
    extern __shared__ char smem[];
    const int z = blockIdx.z;
    const float* bias = (z == 0) ? bq : (z == 1) ? bk : bv;
    __half* out16 = (z == 0) ? g_Qh16 : (z == 1) ? g_Kh16 : g_Vh16;
    gemm_body(g_Xh3[z], g_Xl3[z], g_Wh4[z], g_Wl4[z], bias,
              nullptr, out16, 1, blockIdx.y * BM, blockIdx.x * BN, smem);
}

__global__ __launch_bounds__(256, 1) void o_gemm_kernel(
    const float* __restrict__ bo, float* __restrict__ out)
{
    extern __shared__ char smem[];
    gemm_body(g_Oh, g_Ol, g_Wh4[3], g_Wl4[3], bo,
              out, nullptr, 0, blockIdx.y * BM, blockIdx.x * BN, smem);
}

// ---------------------------------------------------------------------------
// Flash attention v8: fp16 operands.
// S = Q16 K16^T single pass (calibrated err 2.8e-4 via softmax transfer 0.28).
// PV = (Ph + Pl) x V16 : P split fp16 in registers, V single fp16.
// 128 thr / 4 warps / 64 q-rows, KV stage 16KB double-buffered, 3 CTA/SM.
// ---------------------------------------------------------------------------
constexpr int ATTN_SMEM = 2 * 16384;

__global__ __launch_bounds__(128, 3) void attn8_kernel()
{
    extern __shared__ char smc[];
    const uint32_t sb = smem_u32(smc);

    const int tid  = threadIdx.x;
    const int lane = tid & 31;
    const int wid  = tid >> 5;
    const int wm   = wid * 16;
    const int bh   = blockIdx.y;
    const int b    = bh >> 4;
    const int h    = bh & 15;
    const int q0   = blockIdx.x * 64;
    const size_t qkv = (size_t)bh * cS * cD;

    // ---- stage Q (fp16, 8KB) ----
#pragma unroll
    for (int i = 0; i < 4; i++) {
        int u = tid + i * 128;
        int row = u >> 3, un = u & 7;
        uint32_t so = SW128(row * 128 + un * 16);
        *(uint4*)(smc + so) = *(const uint4*)(g_Qh16 + qkv + (size_t)(q0 + row) * cD + un * 8);
    }
    __syncthreads();

    const int qrow = wm + ((lane >> 3) & 1) * 8 + (lane & 7);
    const uint32_t qc   = ((lane >> 4) & 1) * 16;
    const uint32_t qxr  = (qrow & 7) << 4;
    const uint32_t qoff = qrow * 128 + qc;
    uint32_t qh[4][4];
#pragma unroll
    for (int kf = 0; kf < 4; kf++)
        ldsm_x4(qh[kf], sb + ((qoff + kf * 32) ^ qxr));
    __syncthreads();

    const int krow_l = ((lane >> 4) & 1) * 8 + (lane & 7);
    const uint32_t kc    = ((lane >> 3) & 1) * 16;
    const uint32_t kxr   = (krow_l & 7) << 4;
    const uint32_t kbase = krow_l * 128 + kc;

    const int vrow_l = ((lane >> 3) & 1) * 8 + (lane & 7);
    const uint32_t vc    = ((lane >> 4) & 1) * 16;
    const uint32_t vxr   = (vrow_l & 7) << 4;
    const uint32_t vbase = vrow_l * 128 + vc;

    float o[8][4];
#pragma unroll
    for (int nf = 0; nf < 8; nf++)
#pragma unroll
        for (int r = 0; r < 4; r++) o[nf][r] = 0.0f;
    float l0 = 0.0f, l1 = 0.0f;
    const float PMASK = __expf(1e-9f - 8.0f);

    // stage: K16 @0, V16 @8192 (16KB per stage)
    auto stage = [&](int t) {
        uint32_t sd = sb + (t & 1) * 16384;
        const int kt = t * 64;
#pragma unroll
        for (int i = 0; i < 4; i++) {
            int u = tid + i * 128;
            int row = u >> 3, un = u & 7;
            uint32_t so = SW128(row * 128 + un * 16);
            size_t g = (qkv + (size_t)(kt + row) * cD + un * 8) * 2;
            cpa16(sd + so,        (const char*)g_Kh16 + g);
            cpa16(sd + 8192 + so, (const char*)g_Vh16 + g);
        }
        CP_COMMIT();
    };

    stage(0);

    const uint32_t* mb0 = g_Mb + ((size_t)b * cS + (q0 + wm + (lane >> 2))) * (cS / 32);
    const uint32_t* mb1 = mb0 + (size_t)8 * (cS / 32);
    const int kb = (lane & 3) * 2;

    for (int t = 0; t < cS / 64; t++) {
        if (t + 1 < cS / 64) {
            stage(t + 1);
            CP_WAIT(1);
        } else {
            CP_WAIT(0);
        }
        __syncthreads();

        const uint32_t sK = sb + (t & 1) * 16384;
        const uint32_t sV = sK + 8192;

        // ---- S = Q16 K16^T (single pass, 32 MMAs) ----
        float s[8][4];
#pragma unroll
        for (int nf = 0; nf < 8; nf++)
#pragma unroll
            for (int r = 0; r < 4; r++) s[nf][r] = 0.0f;

#pragma unroll
        for (int kf = 0; kf < 4; kf++) {
#pragma unroll
            for (int nb = 0; nb < 4; nb++) {
                uint32_t rh[4];
                ldsm_x4(rh, sK + ((kbase + nb * 2048 + kf * 32) ^ kxr));
                mma_fp16(s[2 * nb],     qh[kf], rh);
                mma_fp16(s[2 * nb + 1], qh[kf], rh + 2);
            }
        }

        // ---- bit-mask + fixed-max exp ----
        uint2 w0 = *(const uint2*)(mb0 + t * 2);
        uint2 w1 = *(const uint2*)(mb1 + t * 2);
#pragma unroll
        for (int nf = 0; nf < 8; nf++) {
            uint32_t ww0 = (nf < 4) ? w0.x : w0.y;
            uint32_t ww1 = (nf < 4) ? w1.x : w1.y;
            int bit = kb + (nf & 3) * 8;
            s[nf][0] = !((ww0 >> bit) & 1)       ? PMASK : __expf(fmaf(s[nf][0], 0.125f, -8.0f));
            s[nf][1] = !((ww0 >> (bit + 1)) & 1) ? PMASK : __expf(fmaf(s[nf][1], 0.125f, -8.0f));
            s[nf][2] = !((ww1 >> bit) & 1)       ? PMASK : __expf(fmaf(s[nf][2], 0.125f, -8.0f));
            s[nf][3] = !((ww1 >> (bit + 1)) & 1) ? PMASK : __expf(fmaf(s[nf][3], 0.125f, -8.0f));
            l0 += s[nf][0] + s[nf][1];
            l1 += s[nf][2] + s[nf][3];
        }

        // ---- O += (Ph + Pl) V16 (P split fp16 in regs; 64 MMAs) ----
#pragma unroll
        for (int kf = 0; kf < 4; kf++) {
            uint32_t ph[4], pl[4];
            ph[0] = packf16(s[2 * kf][0],     s[2 * kf][1]);
            ph[1] = packf16(s[2 * kf][2],     s[2 * kf][3]);
            ph[2] = packf16(s[2 * kf + 1][0], s[2 * kf + 1][1]);
            ph[3] = packf16(s[2 * kf + 1][2], s[2 * kf + 1][3]);
            pl[0] = packf16(s[2 * kf][0]     - f16lo(ph[0]), s[2 * kf][1]     - f16hi(ph[0]));
            pl[1] = packf16(s[2 * kf][2]     - f16lo(ph[1]), s[2 * kf][3]     - f16hi(ph[1]));
            pl[2] = packf16(s[2 * kf + 1][0] - f16lo(ph[2]), s[2 * kf + 1][1] - f16hi(ph[2]));
            pl[3] = packf16(s[2 * kf + 1][2] - f16lo(ph[3]), s[2 * kf + 1][3] - f16hi(ph[3]));
#pragma unroll
            for (int db = 0; db < 4; db++) {
                uint32_t vh[4];
                ldsm_x4_t(vh, sV + ((vbase + kf * 2048 + db * 32) ^ vxr));
                mma_fp16(o[2 * db],     ph, vh);
                mma_fp16(o[2 * db],     pl, vh);
                mma_fp16(o[2 * db + 1], ph, vh + 2);
                mma_fp16(o[2 * db + 1], pl, vh + 2);
            }
        }
        __syncthreads();
    }

    // ---- final l reduction + normalize + write bf16 hi/lo for O-GEMM ----
    l0 += __shfl_xor_sync(0xffffffffu, l0, 1);
    l0 += __shfl_xor_sync(0xffffffffu, l0, 2);
    l1 += __shfl_xor_sync(0xffffffffu, l1, 1);
    l1 += __shfl_xor_sync(0xffffffffu, l1, 2);
    float inv0 = 1.0f / l0, inv1 = 1.0f / l1;
    int row0 = q0 + wm + (lane >> 2);
#pragma unroll
    for (int nf = 0; nf < 8; nf++) {
        int dcol = h * cD + nf * 8 + (lane & 3) * 2;
        size_t i1 = ((size_t)b * cS + row0) * cH + dcol;
        size_t i2 = i1 + (size_t)8 * cH;
        float f0 = o[nf][0] * inv0, f1 = o[nf][1] * inv0;
        float f2 = o[nf][2] * inv1, f3 = o[nf][3] * inv1;
        uint32_t h0 = packbf(f0, f1);
        uint32_t h1 = packbf(f2, f3);
        *(uint32_t*)((char*)g_Oh + i1 * 2) = h0;
        *(uint32_t*)((char*)g_Oh + i2 * 2) = h1;
        *(uint32_t*)((char*)g_Ol + i1 * 2) = packbf(f0 - bflo(h0), f1 - bfhi(h0));
        *(uint32_t*)((char*)g_Ol + i2 * 2) = packbf(f2 - bflo(h1), f3 - bfhi(h1));
    }
}

// ---------------------------------------------------------------------------
extern "C" void kernel_launch(void* const* d_in, const int* in_sizes, int n_in,
                              void* d_out, int out_size)
{
    const float* q    = (const float*)d_in[0];
    const float* k    = (const float*)d_in[1];
    const float* v    = (const float*)d_in[2];
    const int*   mask = (const int*)  d_in[3];
    const float* Wq   = (const float*)d_in[4];
    const float* bq   = (const float*)d_in[5];
    const float* Wk   = (const float*)d_in[6];
    const float* bk   = (const float*)d_in[7];
    const float* Wv   = (const float*)d_in[8];
    const float* bv   = (const float*)d_in[9];
    const float* Wo   = (const float*)d_in[10];
    const float* bo   = (const float*)d_in[11];

    cudaFuncSetAttribute(qkv_gemm_kernel,
                         cudaFuncAttributeMaxDynamicSharedMemorySize, GEMM_SMEM);
    cudaFuncSetAttribute(o_gemm_kernel,
                         cudaFuncAttributeMaxDynamicSharedMemorySize, GEMM_SMEM);
    cudaFuncSetAttribute(attn8_kernel,
                         cudaFuncAttributeMaxDynamicSharedMemorySize, ATTN_SMEM);

    const int nX4 = cM * cH / 4;
    const int nW4 = cH * cH / 4;

    split3x_kernel<<<dim3(nX4 / 256, 3), 256>>>(q, k, v, nX4);
    split4w_kernel<<<dim3(nW4 / 256, 4), 256>>>(Wq, Wk, Wv, Wo, nW4);
    maskpack_kernel<<<(cB * cS * (cS / 32)) / 8, 256>>>(mask);

    qkv_gemm_kernel<<<dim3(cH / BN, cM / BM, 3), 256, GEMM_SMEM>>>(bq, bk, bv);

    attn8_kernel<<<dim3(cS / 64, cB * cNH), 128, ATTN_SMEM>>>();

    o_gemm_kernel<<<dim3(cH / BN, cM / BM), 256, GEMM_SMEM>>>(bo, (float*)d_out);
}